// round 7
// baseline (speedup 1.0000x reference)
#include <cuda_runtime.h>
#include <cstdint>

#define NMAX 100000
#define EMAX 3300000
#define MMAX 8192
#define KINF 0xFFFFFFFFFFFFFFFFULL
#define MAXB 1024
#define NEG0 0x80000000u
#define CHROWS 2048           // dense rows per chunk: 2048*8192*4B = 64 MB window
#define NCHUNK (MMAX / CHROWS)

// ---------------- static device scratch (no allocations allowed) -------------
__device__ unsigned long long g_key[NMAX];
__device__ unsigned long long g_minCur[NMAX];
__device__ unsigned long long g_minNew[NMAX];
__device__ unsigned char g_mask[NMAX];
__device__ unsigned char g_maskP[NMAX];
__device__ unsigned char g_mis[NMAX];
__device__ int g_misIdx[NMAX];
__device__ int g_cluster[NMAX];
__device__ float g_dense[(size_t)MMAX * (size_t)MMAX];   // 256 MB, NEG0 presence
__device__ unsigned long long g_pair[EMAX];              // packed (cr<<13|cc)<<32 | attr
__device__ unsigned long long g_trip[EMAX];              // staged (r<<13|c)<<32 | val
__device__ int g_nodeCnt[MAXB];
__device__ int g_nodeOff[MAXB];
__device__ int g_cellCnt[MAXB];
__device__ int g_cellOff[MAXB];
__device__ int g_cnt2[2];
__device__ unsigned long long g_maxMisKey;
__device__ int g_M;
__device__ int g_P;
__device__ unsigned int g_arrive;

// ---------------- helpers ----------------------------------------------------

__device__ __forceinline__ void grid_bar(unsigned nb, unsigned &target) {
    __threadfence();
    __syncthreads();
    if (threadIdx.x == 0) {
        target += nb;
        atomicAdd(&g_arrive, 1u);
        while (*((volatile unsigned*)&g_arrive) < target) __nanosleep(64);
        __threadfence();
    }
    __syncthreads();
}

__device__ __forceinline__ int block_reduce_add(int v) {
    __shared__ int shr[32];
    int lane = threadIdx.x & 31;
    int w = threadIdx.x >> 5;
    #pragma unroll
    for (int o = 16; o; o >>= 1) v += __shfl_down_sync(0xffffffffu, v, o);
    if (lane == 0) shr[w] = v;
    __syncthreads();
    int nw = (blockDim.x + 31) >> 5;
    int r = 0;
    if (w == 0) {
        r = (lane < nw) ? shr[lane] : 0;
        #pragma unroll
        for (int o = 16; o; o >>= 1) r += __shfl_down_sync(0xffffffffu, r, o);
    }
    __syncthreads();
    return r;  // valid on threadIdx.x == 0
}

__device__ __forceinline__ int block_excl_scan(int v, int &total) {
    __shared__ int sh[1024];
    int t = threadIdx.x;
    sh[t] = v;
    __syncthreads();
    for (int off = 1; off < blockDim.x; off <<= 1) {
        int y = (t >= off) ? sh[t - off] : 0;
        __syncthreads();
        sh[t] += y;
        __syncthreads();
    }
    int incl = sh[t];
    total = sh[blockDim.x - 1];
    __syncthreads();
    return incl - v;
}

// read-filtered atomicMin: stale read >= actual, so skipping when mv >= cur is safe.
__device__ __forceinline__ void propF(int row, int col) {
    unsigned long long mv = g_minCur[row];
    if (mv != KINF) {
        unsigned long long c = g_minNew[col];
        if (mv < c) atomicMin(&g_minNew[col], mv);
    }
}
__device__ __forceinline__ void dil(int row, int col) {
    if (g_mask[row]) g_maskP[col] = 1;
}

// ---------------- kernels -----------------------------------------------------

__global__ void k_init(const float* __restrict__ score, int n) {
    int v = blockIdx.x * blockDim.x + threadIdx.x;
    if (v < n) {
        unsigned long long k =
            ((unsigned long long)__float_as_uint(score[v]) << 32) | (unsigned)v;
        g_key[v] = k; g_minCur[v] = k; g_minNew[v] = k;
        g_mask[v] = 0; g_maskP[v] = 0; g_mis[v] = 0;
    }
    if (v == 0) {
        g_arrive = 0;
        g_cnt2[0] = 0; g_cnt2[1] = 1;   // slot 1 read at top of round 0
        g_maxMisKey = 0; g_M = 0; g_P = 0;
    }
}

// Persistent kernel: full MIS loop + clustering (R1-proven structure).
__global__ void __launch_bounds__(256, 4)
k_persist(const int* __restrict__ erow, const int* __restrict__ ecol,
          int n, int e, const float* __restrict__ x, int d,
          float* __restrict__ out)
{
    const unsigned nb = gridDim.x;
    const unsigned nt = nb * blockDim.x;
    const unsigned tid = blockIdx.x * blockDim.x + threadIdx.x;
    unsigned bt = 0;
    const bool vecok = ((e & 3) == 0);
    const unsigned e4 = (unsigned)e >> 2;

    for (int round = 0; round < 100000; ++round) {
        if (*((volatile int*)&g_cnt2[(round + 1) & 1]) == 0) break;

        // A: min-key propagation
        if (vecok) {
            for (unsigned i = tid; i < e4; i += nt) {
                int4 r = __ldg((const int4*)erow + i);
                int4 c = __ldg((const int4*)ecol + i);
                propF(r.x, c.x); propF(r.y, c.y);
                propF(r.z, c.z); propF(r.w, c.w);
            }
        } else {
            for (unsigned i = tid; i < (unsigned)e; i += nt)
                propF(erow[i], ecol[i]);
        }
        grid_bar(nb, bt);

        // B: local minima join MIS
        if (tid == 0) g_cnt2[(round + 1) & 1] = 0;
        for (unsigned v = tid; v < (unsigned)n; v += nt) {
            unsigned char m = g_mask[v];
            if (!m && g_key[v] == g_minNew[v]) { g_mis[v] = 1; g_mask[v] = 1; m = 1; }
            g_maskP[v] = m;
        }
        grid_bar(nb, bt);

        // C: mask dilation by exactly 1 hop
        if (vecok) {
            for (unsigned i = tid; i < e4; i += nt) {
                int4 r = __ldg((const int4*)erow + i);
                int4 c = __ldg((const int4*)ecol + i);
                dil(r.x, c.x); dil(r.y, c.y); dil(r.z, c.z); dil(r.w, c.w);
            }
        } else {
            for (unsigned i = tid; i < (unsigned)e; i += nt)
                dil(erow[i], ecol[i]);
        }
        grid_bar(nb, bt);

        // D: commit mask, reset min arrays, count unmasked
        int local = 0;
        for (unsigned v = tid; v < (unsigned)n; v += nt) {
            unsigned char m = g_maskP[v];
            g_mask[v] = m;
            unsigned long long val = m ? KINF : g_key[v];
            g_minCur[v] = val; g_minNew[v] = val;
            local += (m == 0);
        }
        int bs = block_reduce_add(local);
        if (threadIdx.x == 0 && bs) atomicAdd(&g_cnt2[round & 1], bs);
        grid_bar(nb, bt);
    }

    // ---------------- clustering ---------------------------------------------
    for (unsigned v = tid; v < (unsigned)n; v += nt) {
        unsigned long long mc;
        if (g_mis[v]) { mc = g_key[v]; atomicMax(&g_maxMisKey, mc); }
        else mc = KINF;
        g_minCur[v] = mc; g_minNew[v] = mc;
    }
    int chunk = (n + (int)nb - 1) / (int)nb;
    int cs = (int)blockIdx.x * chunk;
    int ce = cs + chunk; if (ce > n) ce = n;
    {
        int cnt = 0;
        for (int v = cs + (int)threadIdx.x; v < ce; v += (int)blockDim.x)
            cnt += g_mis[v];
        int bs = block_reduce_add(cnt);
        if (threadIdx.x == 0) g_nodeCnt[blockIdx.x] = bs;
    }
    grid_bar(nb, bt);

    if (blockIdx.x == 0 && threadIdx.x == 0) {
        int s = 0;
        for (unsigned i = 0; i < nb; ++i) { int c = g_nodeCnt[i]; g_nodeOff[i] = s; s += c; }
        if (s > MMAX) s = MMAX;
        g_M = s;
    }
    grid_bar(nb, bt);

    {
        int run = g_nodeOff[blockIdx.x];
        for (int t0 = cs; t0 < ce; t0 += (int)blockDim.x) {
            int v = t0 + (int)threadIdx.x;
            int f = (v < ce) ? (int)g_mis[v] : 0;
            int tot;
            int ex = block_excl_scan(f, tot);
            if (v < ce) g_misIdx[v] = run + ex;
            run += tot;
        }
    }
    grid_bar(nb, bt);

    // H: one min-key propagation (k = 1), full edge list
    if (vecok) {
        for (unsigned i = tid; i < e4; i += nt) {
            int4 r = __ldg((const int4*)erow + i);
            int4 c = __ldg((const int4*)ecol + i);
            propF(r.x, c.x); propF(r.y, c.y); propF(r.z, c.z); propF(r.w, c.w);
        }
    } else {
        for (unsigned i = tid; i < (unsigned)e; i += nt)
            propF(erow[i], ecol[i]);
    }
    grid_bar(nb, bt);

    // I: cluster assignment
    int fb = g_misIdx[(unsigned)(g_maxMisKey & 0xffffffffULL)];
    for (unsigned v = tid; v < (unsigned)n; v += nt) {
        unsigned long long mk = g_minNew[v];
        g_cluster[v] = (mk == KINF) ? fb : g_misIdx[(unsigned)(mk & 0xffffffffULL)];
    }

    // J: x_out = x[mis]
    if ((d & 3) == 0) {
        int dv = d >> 2;
        for (unsigned v = tid; v < (unsigned)n; v += nt) {
            if (g_mis[v]) {
                const float4* src = (const float4*)(x + (size_t)v * d);
                float4* dst = (float4*)(out + (size_t)g_misIdx[v] * d);
                for (int j = 0; j < dv; ++j) dst[j] = src[j];
            }
        }
    } else {
        for (unsigned v = tid; v < (unsigned)n; v += nt) {
            if (g_mis[v]) {
                const float* src = x + (size_t)v * d;
                float* dst = out + (size_t)g_misIdx[v] * d;
                for (int j = 0; j < d; ++j) dst[j] = src[j];
            }
        }
    }
}

// ---------------- chunked dense pipeline (L2-resident atomics) ----------------

// Pack (cr<<13|cc, attr) per edge — gathers hit L2-resident cluster array.
__global__ void k_pack(const int* __restrict__ erow, const int* __restrict__ ecol,
                       const float* __restrict__ attr, int e) {
    unsigned nt = gridDim.x * blockDim.x;
    unsigned t = blockIdx.x * blockDim.x + threadIdx.x;
    if ((e & 3) == 0) {
        unsigned e4 = (unsigned)e >> 2;
        for (unsigned i = t; i < e4; i += nt) {
            int4 r = __ldg((const int4*)erow + i);
            int4 c = __ldg((const int4*)ecol + i);
            float4 a = __ldg((const float4*)attr + i);
            unsigned k0 = ((unsigned)g_cluster[r.x] << 13) | (unsigned)g_cluster[c.x];
            unsigned k1 = ((unsigned)g_cluster[r.y] << 13) | (unsigned)g_cluster[c.y];
            unsigned k2 = ((unsigned)g_cluster[r.z] << 13) | (unsigned)g_cluster[c.z];
            unsigned k3 = ((unsigned)g_cluster[r.w] << 13) | (unsigned)g_cluster[c.w];
            g_pair[4*i+0] = ((unsigned long long)k0 << 32) | __float_as_uint(a.x);
            g_pair[4*i+1] = ((unsigned long long)k1 << 32) | __float_as_uint(a.y);
            g_pair[4*i+2] = ((unsigned long long)k2 << 32) | __float_as_uint(a.z);
            g_pair[4*i+3] = ((unsigned long long)k3 << 32) | __float_as_uint(a.w);
        }
    } else {
        for (unsigned i = t; i < (unsigned)e; i += nt) {
            unsigned k = ((unsigned)g_cluster[erow[i]] << 13) | (unsigned)g_cluster[ecol[i]];
            g_pair[i] = ((unsigned long long)k << 32) | __float_as_uint(attr[i]);
        }
    }
}

// Zero one chunk window (rows [ch*CHROWS, min((ch+1)*CHROWS, M)) of dense[M x M]).
__global__ void k_zeroC(int ch) {
    int M = g_M;
    int r0 = ch * CHROWS;
    if (r0 >= M) return;
    int r1 = r0 + CHROWS; if (r1 > M) r1 = M;
    size_t s = (size_t)r0 * M;
    size_t epos = (size_t)r1 * M;
    size_t nt = (size_t)gridDim.x * blockDim.x;
    float neg0 = __uint_as_float(NEG0);
    for (size_t i = s + (size_t)blockIdx.x * blockDim.x + threadIdx.x; i < epos; i += nt)
        g_dense[i] = neg0;
}

// RED filtered edges into the (L2-resident) chunk window.
// Edge belongs to chunk ch iff cr>>11 == ch, i.e. k>>24 == ch (cr = k>>13, CHROWS=2048).
__global__ void k_accumC(int ch, int e) {
    int M = g_M;
    if (ch * CHROWS >= M) return;
    unsigned nt = gridDim.x * blockDim.x;
    unsigned t = blockIdx.x * blockDim.x + threadIdx.x;
    for (unsigned i = t; i < (unsigned)e; i += nt) {
        unsigned long long p = g_pair[i];
        unsigned k = (unsigned)(p >> 32);
        if ((k >> 24) != (unsigned)ch) continue;    // FIXED chunk filter
        unsigned cr = k >> 13, cc = k & 8191u;
        atomicAdd(&g_dense[(size_t)cr * M + cc], __uint_as_float((unsigned)p));
    }
}

// Count present off-diagonal cells in the chunk window (per-block counts).
__global__ void k_countC(int ch) {
    int M = g_M;
    int r0 = ch * CHROWS;
    if (r0 >= M) { if (threadIdx.x == 0) g_cellCnt[blockIdx.x] = 0; return; }
    int r1 = r0 + CHROWS; if (r1 > M) r1 = M;
    size_t base = (size_t)r0 * M;
    size_t cells = (size_t)(r1 - r0) * M;
    size_t chunkC = (cells + gridDim.x - 1) / gridDim.x;
    size_t s = (size_t)blockIdx.x * chunkC;
    size_t epos = s + chunkC; if (epos > cells) epos = cells;
    int cnt = 0;
    for (size_t i = s + threadIdx.x; i < epos; i += blockDim.x) {
        if (__float_as_uint(g_dense[base + i]) != NEG0) {
            unsigned ii = (unsigned)i;
            unsigned r = r0 + ii / (unsigned)M, c = ii % (unsigned)M;
            cnt += (r != c);
        }
    }
    int bs = block_reduce_add(cnt);
    if (threadIdx.x == 0) g_cellCnt[blockIdx.x] = bs;
}

// Scan per-block counts; offsets continue from running g_P. 1 block.
__global__ void k_scanC() {
    int t = threadIdx.x;
    int v = (t < MAXB) ? g_cellCnt[t] : 0;
    int tot;
    int ex = block_excl_scan(v, tot);
    int base = g_P;
    if (t < MAXB) g_cellOff[t] = base + ex;
    __syncthreads();
    if (t == 0) g_P = base + tot;
}

// Write chunk's present cells as packed triples into staging (lex order kept).
__global__ void k_writeC(int ch) {
    int M = g_M;
    int r0 = ch * CHROWS;
    if (r0 >= M) return;
    int r1 = r0 + CHROWS; if (r1 > M) r1 = M;
    size_t gbase = (size_t)r0 * M;
    size_t cells = (size_t)(r1 - r0) * M;
    size_t chunkC = (cells + gridDim.x - 1) / gridDim.x;
    size_t s = (size_t)blockIdx.x * chunkC;
    size_t epos = s + chunkC; if (epos > cells) epos = cells;
    size_t wbase = (size_t)g_cellOff[blockIdx.x];
    for (size_t t0 = s; t0 < epos; t0 += blockDim.x) {
        size_t i = t0 + threadIdx.x;
        int keep = 0; unsigned rc = 0; unsigned vbits = 0;
        if (i < epos) {
            float fv = g_dense[gbase + i];
            if (__float_as_uint(fv) != NEG0) {
                unsigned ii = (unsigned)i;
                unsigned r = r0 + ii / (unsigned)M, c = ii % (unsigned)M;
                if (r != c) { keep = 1; rc = (r << 13) | c; vbits = __float_as_uint(fv); }
            }
        }
        int tot;
        int ex = block_excl_scan(keep, tot);
        if (keep)
            g_trip[wbase + ex] = ((unsigned long long)rc << 32) | vbits;
        wbase += tot;
    }
}

// Copy staging triples to the output layout (needs final P).
__global__ void k_finalize(float* __restrict__ out, int d) {
    size_t P = (size_t)g_P;
    size_t xoff = (size_t)g_M * (size_t)d;
    size_t nt = (size_t)gridDim.x * blockDim.x;
    for (size_t p = (size_t)blockIdx.x * blockDim.x + threadIdx.x; p < P; p += nt) {
        unsigned long long t = g_trip[p];
        unsigned rc = (unsigned)(t >> 32);
        out[xoff + p] = (float)(rc >> 13);
        out[xoff + P + p] = (float)(rc & 8191u);
        out[xoff + 2 * P + p] = __uint_as_float((unsigned)t);
    }
}

__global__ void k_tail(float* __restrict__ out, const float* __restrict__ score,
                       int n, int d) {
    int v = blockIdx.x * blockDim.x + threadIdx.x;
    if (v >= n) return;
    size_t off = (size_t)g_M * (size_t)d + 3 * (size_t)g_P;
    out[off + v] = (float)g_cluster[v];
    out[off + (size_t)n + v] = g_mis[v] ? 1.0f : 0.0f;
    out[off + 2 * (size_t)n + v] = score[v];
}

// ---------------- entry -------------------------------------------------------
extern "C" void kernel_launch(void* const* d_in, const int* in_sizes, int n_in,
                              void* d_out, int out_size) {
    const float* x = (const float*)d_in[0];
    const int* ei = (const int*)d_in[1];
    const float* attr = (const float*)d_in[2];
    const float* score = (const float*)d_in[3];
    int n = in_sizes[3];
    int e = in_sizes[1] / 2;
    int d = in_sizes[0] / n;
    const int* erow = ei;
    const int* ecol = ei + e;
    float* out = (float*)d_out;

    int dev = 0;
    cudaGetDevice(&dev);
    int sms = 148;
    cudaDeviceGetAttribute(&sms, cudaDevAttrMultiProcessorCount, dev);
    int nb = sms * 4;
    if (nb > MAXB) nb = MAXB;

    k_init<<<(n + 255) / 256, 256>>>(score, n);
    k_persist<<<nb, 256>>>(erow, ecol, n, e, x, d, out);
    k_pack<<<4096, 256>>>(erow, ecol, attr, e);
    for (int ch = 0; ch < NCHUNK; ++ch) {
        k_zeroC<<<2048, 256>>>(ch);
        k_accumC<<<2048, 256>>>(ch, e);
        k_countC<<<MAXB, 256>>>(ch);
        k_scanC<<<1, 1024>>>();
        k_writeC<<<MAXB, 256>>>(ch);
    }
    k_finalize<<<2048, 256>>>(out, d);
    k_tail<<<(n + 255) / 256, 256>>>(out, score, n, d);
}

// round 8
// speedup vs baseline: 1.2903x; 1.2903x over previous
#include <cuda_runtime.h>
#include <cstdint>

#define NMAX 100000
#define EMAX 3300000
#define MMAX 8192
#define KINF 0xFFFFFFFFFFFFFFFFULL
#define MAXB 1024
#define NEG0 0x80000000u

// ---------------- static device scratch (no allocations allowed) -------------
__device__ unsigned long long g_key[NMAX];
__device__ unsigned long long g_minCur[NMAX];
__device__ unsigned long long g_minNew[NMAX];
__device__ unsigned char g_mask[NMAX];
__device__ unsigned char g_maskP[NMAX];
__device__ unsigned char g_mis[NMAX];
__device__ int g_misIdx[NMAX];
__device__ int g_cluster[NMAX];
__device__ float g_dense[(size_t)MMAX * (size_t)MMAX];   // 256 MB, NEG0 presence
__device__ unsigned long long g_liveE[EMAX];             // live edges after round 0
__device__ int g_nodeCnt[MAXB];
__device__ int g_nodeOff[MAXB];
__device__ int g_cellCnt[MAXB];
__device__ int g_cellOff[MAXB];
__device__ int g_cnt2[2];
__device__ int g_liveCnt;
__device__ unsigned long long g_maxMisKey;
__device__ int g_M;
__device__ int g_P;
__device__ unsigned int g_arrive;

// ---------------- helpers ----------------------------------------------------

__device__ __forceinline__ void grid_bar(unsigned nb, unsigned &target) {
    __threadfence();
    __syncthreads();
    if (threadIdx.x == 0) {
        target += nb;
        atomicAdd(&g_arrive, 1u);
        while (*((volatile unsigned*)&g_arrive) < target) __nanosleep(64);
        __threadfence();
    }
    __syncthreads();
}

__device__ __forceinline__ int block_reduce_add(int v) {
    __shared__ int shr[32];
    int lane = threadIdx.x & 31;
    int w = threadIdx.x >> 5;
    #pragma unroll
    for (int o = 16; o; o >>= 1) v += __shfl_down_sync(0xffffffffu, v, o);
    if (lane == 0) shr[w] = v;
    __syncthreads();
    int nw = (blockDim.x + 31) >> 5;
    int r = 0;
    if (w == 0) {
        r = (lane < nw) ? shr[lane] : 0;
        #pragma unroll
        for (int o = 16; o; o >>= 1) r += __shfl_down_sync(0xffffffffu, r, o);
    }
    __syncthreads();
    return r;  // valid on threadIdx.x == 0
}

__device__ __forceinline__ int block_excl_scan(int v, int &total) {
    __shared__ int sh[1024];
    int t = threadIdx.x;
    sh[t] = v;
    __syncthreads();
    for (int off = 1; off < blockDim.x; off <<= 1) {
        int y = (t >= off) ? sh[t - off] : 0;
        __syncthreads();
        sh[t] += y;
        __syncthreads();
    }
    int incl = sh[t];
    total = sh[blockDim.x - 1];
    __syncthreads();
    return incl - v;
}

// read-filtered atomicMin: stale read >= actual, so skipping when mv >= cur is safe.
__device__ __forceinline__ void propF(int row, int col) {
    unsigned long long mv = g_minCur[row];
    if (mv != KINF) {
        unsigned long long c = g_minNew[col];
        if (mv < c) atomicMin(&g_minNew[col], mv);
    }
}
__device__ __forceinline__ void dil(int row, int col) {
    if (g_mask[row]) g_maskP[col] = 1;
}

// ---------------- kernels -----------------------------------------------------

__global__ void k_init(const float* __restrict__ score, int n) {
    int v = blockIdx.x * blockDim.x + threadIdx.x;
    if (v < n) {
        unsigned long long k =
            ((unsigned long long)__float_as_uint(score[v]) << 32) | (unsigned)v;
        g_key[v] = k; g_minCur[v] = k; g_minNew[v] = k;
        g_mask[v] = 0; g_maskP[v] = 0; g_mis[v] = 0;
    }
    if (v == 0) {
        g_arrive = 0;
        g_cnt2[0] = 0; g_cnt2[1] = 1;   // slot 1 read at top of round 0
        g_maxMisKey = 0; g_M = 0; g_P = 0; g_liveCnt = 0;
    }
}

// Persistent kernel: full MIS loop + clustering. Round 0 scans full edge arrays;
// afterwards a ONE-TIME compaction keeps only edges into unmasked cols, so
// rounds >= 1 touch ~3% of the edges (kills the per-round random-gather cost).
__global__ void __launch_bounds__(256, 4)
k_persist(const int* __restrict__ erow, const int* __restrict__ ecol,
          int n, int e, const float* __restrict__ x, int d,
          float* __restrict__ out)
{
    const unsigned nb = gridDim.x;
    const unsigned nt = nb * blockDim.x;
    const unsigned tid = blockIdx.x * blockDim.x + threadIdx.x;
    unsigned bt = 0;
    const bool vecok = ((e & 3) == 0);
    const unsigned e4 = (unsigned)e >> 2;
    unsigned live = 0;

    for (int round = 0; round < 100000; ++round) {
        if (*((volatile int*)&g_cnt2[(round + 1) & 1]) == 0) break;

        // A: min-key propagation
        if (round == 0) {
            if (vecok) {
                for (unsigned i = tid; i < e4; i += nt) {
                    int4 r = __ldg((const int4*)erow + i);
                    int4 c = __ldg((const int4*)ecol + i);
                    propF(r.x, c.x); propF(r.y, c.y);
                    propF(r.z, c.z); propF(r.w, c.w);
                }
            } else {
                for (unsigned i = tid; i < (unsigned)e; i += nt)
                    propF(erow[i], ecol[i]);
            }
        } else {
            for (unsigned i = tid; i < live; i += nt) {
                unsigned long long p = g_liveE[i];
                propF((int)(p >> 32), (int)(unsigned)p);
            }
        }
        grid_bar(nb, bt);

        // B: local minima join MIS
        if (tid == 0) g_cnt2[(round + 1) & 1] = 0;
        for (unsigned v = tid; v < (unsigned)n; v += nt) {
            unsigned char m = g_mask[v];
            if (!m && g_key[v] == g_minNew[v]) { g_mis[v] = 1; g_mask[v] = 1; m = 1; }
            g_maskP[v] = m;
        }
        grid_bar(nb, bt);

        // C: mask dilation by exactly 1 hop
        if (round == 0) {
            if (vecok) {
                for (unsigned i = tid; i < e4; i += nt) {
                    int4 r = __ldg((const int4*)erow + i);
                    int4 c = __ldg((const int4*)ecol + i);
                    dil(r.x, c.x); dil(r.y, c.y); dil(r.z, c.z); dil(r.w, c.w);
                }
            } else {
                for (unsigned i = tid; i < (unsigned)e; i += nt)
                    dil(erow[i], ecol[i]);
            }
        } else {
            for (unsigned i = tid; i < live; i += nt) {
                unsigned long long p = g_liveE[i];
                dil((int)(p >> 32), (int)(unsigned)p);
            }
        }
        grid_bar(nb, bt);

        // D: commit mask, reset min arrays, count unmasked
        int local = 0;
        for (unsigned v = tid; v < (unsigned)n; v += nt) {
            unsigned char m = g_maskP[v];
            g_mask[v] = m;
            unsigned long long val = m ? KINF : g_key[v];
            g_minCur[v] = val; g_minNew[v] = val;
            local += (m == 0);
        }
        int bs = block_reduce_add(local);
        if (threadIdx.x == 0 && bs) atomicAdd(&g_cnt2[round & 1], bs);
        grid_bar(nb, bt);

        // ONE-TIME compaction after round 0: keep edges whose col is unmasked.
        // (Dropped edges target masked cols: A-writes there are dead, C-dilation
        // there is a no-op since maskP already 1. Mask only grows, so the list
        // stays valid for all later rounds. Final H uses the FULL edge arrays.)
        if (round == 0) {
            unsigned eR = ((unsigned)e + 31u) & ~31u;
            int lane = threadIdx.x & 31;
            for (unsigned i = tid; i < eR; i += nt) {
                int keep = 0; int r = 0, c = 0;
                if (i < (unsigned)e) {
                    c = ecol[i];
                    if (!g_mask[c]) { keep = 1; r = erow[i]; }
                }
                unsigned bal = __ballot_sync(0xffffffffu, keep);
                int base = 0;
                if (lane == 0 && bal) base = atomicAdd(&g_liveCnt, __popc(bal));
                base = __shfl_sync(0xffffffffu, base, 0);
                if (keep)
                    g_liveE[base + __popc(bal & ((1u << lane) - 1u))] =
                        ((unsigned long long)(unsigned)r << 32) | (unsigned)c;
            }
            grid_bar(nb, bt);
            live = (unsigned)(*((volatile int*)&g_liveCnt));
        }
    }

    // ---------------- clustering ---------------------------------------------
    for (unsigned v = tid; v < (unsigned)n; v += nt) {
        unsigned long long mc;
        if (g_mis[v]) { mc = g_key[v]; atomicMax(&g_maxMisKey, mc); }
        else mc = KINF;
        g_minCur[v] = mc; g_minNew[v] = mc;
    }
    int chunk = (n + (int)nb - 1) / (int)nb;
    int cs = (int)blockIdx.x * chunk;
    int ce = cs + chunk; if (ce > n) ce = n;
    {
        int cnt = 0;
        for (int v = cs + (int)threadIdx.x; v < ce; v += (int)blockDim.x)
            cnt += g_mis[v];
        int bs = block_reduce_add(cnt);
        if (threadIdx.x == 0) g_nodeCnt[blockIdx.x] = bs;
    }
    grid_bar(nb, bt);

    if (blockIdx.x == 0 && threadIdx.x == 0) {
        int s = 0;
        for (unsigned i = 0; i < nb; ++i) { int c = g_nodeCnt[i]; g_nodeOff[i] = s; s += c; }
        if (s > MMAX) s = MMAX;
        g_M = s;
    }
    grid_bar(nb, bt);

    {
        int run = g_nodeOff[blockIdx.x];
        for (int t0 = cs; t0 < ce; t0 += (int)blockDim.x) {
            int v = t0 + (int)threadIdx.x;
            int f = (v < ce) ? (int)g_mis[v] : 0;
            int tot;
            int ex = block_excl_scan(f, tot);
            if (v < ce) g_misIdx[v] = run + ex;
            run += tot;
        }
    }
    grid_bar(nb, bt);

    // H: one min-key propagation (k = 1), full edge list
    if (vecok) {
        for (unsigned i = tid; i < e4; i += nt) {
            int4 r = __ldg((const int4*)erow + i);
            int4 c = __ldg((const int4*)ecol + i);
            propF(r.x, c.x); propF(r.y, c.y); propF(r.z, c.z); propF(r.w, c.w);
        }
    } else {
        for (unsigned i = tid; i < (unsigned)e; i += nt)
            propF(erow[i], ecol[i]);
    }
    grid_bar(nb, bt);

    // I: cluster assignment
    int fb = g_misIdx[(unsigned)(g_maxMisKey & 0xffffffffULL)];
    for (unsigned v = tid; v < (unsigned)n; v += nt) {
        unsigned long long mk = g_minNew[v];
        g_cluster[v] = (mk == KINF) ? fb : g_misIdx[(unsigned)(mk & 0xffffffffULL)];
    }

    // J: x_out = x[mis]
    if ((d & 3) == 0) {
        int dv = d >> 2;
        for (unsigned v = tid; v < (unsigned)n; v += nt) {
            if (g_mis[v]) {
                const float4* src = (const float4*)(x + (size_t)v * d);
                float4* dst = (float4*)(out + (size_t)g_misIdx[v] * d);
                for (int j = 0; j < dv; ++j) dst[j] = src[j];
            }
        }
    } else {
        for (unsigned v = tid; v < (unsigned)n; v += nt) {
            if (g_mis[v]) {
                const float* src = x + (size_t)v * d;
                float* dst = out + (size_t)g_misIdx[v] * d;
                for (int j = 0; j < d; ++j) dst[j] = src[j];
            }
        }
    }
}

// ---------------- dense pipeline (R1/R5-proven, NEG0 presence) ----------------

__global__ void k_zero() {
    size_t MM = (size_t)g_M * (size_t)g_M;
    size_t nt = (size_t)gridDim.x * blockDim.x;
    float neg0 = __uint_as_float(NEG0);
    for (size_t i = (size_t)blockIdx.x * blockDim.x + threadIdx.x; i < MM; i += nt)
        g_dense[i] = neg0;
}

__global__ void k_accum(const int* __restrict__ erow, const int* __restrict__ ecol,
                        const float* __restrict__ attr, int e) {
    unsigned M = (unsigned)g_M;
    unsigned nt = gridDim.x * blockDim.x;
    unsigned t = blockIdx.x * blockDim.x + threadIdx.x;
    if ((e & 3) == 0) {
        unsigned e4 = (unsigned)e >> 2;
        for (unsigned i = t; i < e4; i += nt) {
            int4 r = __ldg((const int4*)erow + i);
            int4 c = __ldg((const int4*)ecol + i);
            float4 a = __ldg((const float4*)attr + i);
            unsigned i0 = (unsigned)g_cluster[r.x] * M + (unsigned)g_cluster[c.x];
            unsigned i1 = (unsigned)g_cluster[r.y] * M + (unsigned)g_cluster[c.y];
            unsigned i2 = (unsigned)g_cluster[r.z] * M + (unsigned)g_cluster[c.z];
            unsigned i3 = (unsigned)g_cluster[r.w] * M + (unsigned)g_cluster[c.w];
            atomicAdd(&g_dense[i0], a.x);
            atomicAdd(&g_dense[i1], a.y);
            atomicAdd(&g_dense[i2], a.z);
            atomicAdd(&g_dense[i3], a.w);
        }
    } else {
        for (unsigned i = t; i < (unsigned)e; i += nt) {
            unsigned idx = (unsigned)g_cluster[erow[i]] * M + (unsigned)g_cluster[ecol[i]];
            atomicAdd(&g_dense[idx], attr[i]);
        }
    }
}

__global__ void k_count() {
    unsigned M = (unsigned)g_M;
    size_t MM = (size_t)M * M;
    size_t chunk = (MM + gridDim.x - 1) / gridDim.x;
    size_t s = (size_t)blockIdx.x * chunk;
    size_t epos = s + chunk; if (epos > MM) epos = MM;
    int cnt = 0;
    for (size_t i = s + threadIdx.x; i < epos; i += blockDim.x) {
        if (__float_as_uint(g_dense[i]) != NEG0) {
            unsigned ii = (unsigned)i;
            unsigned r = ii / M, c = ii - r * M;
            cnt += (r != c);
        }
    }
    int bs = block_reduce_add(cnt);
    if (threadIdx.x == 0) g_cellCnt[blockIdx.x] = bs;
}

__global__ void k_scan(int nb2) {
    int t = threadIdx.x;
    int v = (t < nb2) ? g_cellCnt[t] : 0;
    int tot;
    int ex = block_excl_scan(v, tot);
    if (t < nb2) g_cellOff[t] = ex;
    if (t == 0) g_P = tot;
}

__global__ void k_write(float* __restrict__ out, int d) {
    unsigned M = (unsigned)g_M;
    size_t MM = (size_t)M * M;
    size_t P = (size_t)g_P;
    size_t xoff = (size_t)M * (size_t)d;
    size_t chunk = (MM + gridDim.x - 1) / gridDim.x;
    size_t s = (size_t)blockIdx.x * chunk;
    size_t epos = s + chunk; if (epos > MM) epos = MM;
    size_t base = (size_t)g_cellOff[blockIdx.x];
    for (size_t t0 = s; t0 < epos; t0 += blockDim.x) {
        size_t i = t0 + threadIdx.x;
        int keep = 0; unsigned r = 0, c = 0; float val = 0.f;
        if (i < epos) {
            float fv = g_dense[i];
            if (__float_as_uint(fv) != NEG0) {
                unsigned ii = (unsigned)i;
                r = ii / M; c = ii - r * M;
                if (r != c) { keep = 1; val = fv; }
            }
        }
        int tot;
        int ex = block_excl_scan(keep, tot);
        if (keep) {
            size_t p = base + (size_t)ex;
            out[xoff + p] = (float)r;
            out[xoff + P + p] = (float)c;
            out[xoff + 2 * P + p] = val;
        }
        base += tot;
    }
}

__global__ void k_tail(float* __restrict__ out, const float* __restrict__ score,
                       int n, int d) {
    int v = blockIdx.x * blockDim.x + threadIdx.x;
    if (v >= n) return;
    size_t off = (size_t)g_M * (size_t)d + 3 * (size_t)g_P;
    out[off + v] = (float)g_cluster[v];
    out[off + (size_t)n + v] = g_mis[v] ? 1.0f : 0.0f;
    out[off + 2 * (size_t)n + v] = score[v];
}

// ---------------- entry -------------------------------------------------------
extern "C" void kernel_launch(void* const* d_in, const int* in_sizes, int n_in,
                              void* d_out, int out_size) {
    const float* x = (const float*)d_in[0];
    const int* ei = (const int*)d_in[1];
    const float* attr = (const float*)d_in[2];
    const float* score = (const float*)d_in[3];
    int n = in_sizes[3];
    int e = in_sizes[1] / 2;
    int d = in_sizes[0] / n;
    const int* erow = ei;
    const int* ecol = ei + e;
    float* out = (float*)d_out;

    int dev = 0;
    cudaGetDevice(&dev);
    int sms = 148;
    cudaDeviceGetAttribute(&sms, cudaDevAttrMultiProcessorCount, dev);
    int nb = sms * 4;
    if (nb > MAXB) nb = MAXB;

    k_init<<<(n + 255) / 256, 256>>>(score, n);
    k_persist<<<nb, 256>>>(erow, ecol, n, e, x, d, out);
    k_zero<<<2048, 256>>>();
    k_accum<<<sms * 8, 256>>>(erow, ecol, attr, e);
    k_count<<<MAXB, 256>>>();
    k_scan<<<1, 1024>>>(MAXB);
    k_write<<<MAXB, 256>>>(out, d);
    k_tail<<<(n + 255) / 256, 256>>>(out, score, n, d);
}